// round 6
// baseline (speedup 1.0000x reference)
#include <cuda_runtime.h>
#include <stdint.h>
#include <math.h>
#include <mma.h>

using namespace nvcuda;

#define BB 2
#define TT 2048
#define DD 1024
#define HH 16
#define DH 64
#define BT (BB*TT)

// Scratch (allocation-free rule: __device__ globals)
__device__ float g_qkv[(size_t)BT * 3 * DD];
__device__ float g_q[(size_t)BT * DD];   // [B,H,T,DH]
__device__ float g_k[(size_t)BT * DD];
__device__ float g_v[(size_t)BT * DD];
__device__ float g_att[(size_t)BT * DD]; // [B*T, D]

// ---------------------------------------------------------------------------
// cp.async helpers
// ---------------------------------------------------------------------------
__device__ __forceinline__ void cp_async16(void* dst, const void* src) {
    unsigned int d = (unsigned int)__cvta_generic_to_shared(dst);
    asm volatile("cp.async.ca.shared.global [%0], [%1], 16;\n" :: "r"(d), "l"(src));
}
__device__ __forceinline__ void cp_commit() {
    asm volatile("cp.async.commit_group;\n");
}
__device__ __forceinline__ void cp_wait1() {
    asm volatile("cp.async.wait_group 1;\n");
}

// Fast exp for x <= 0: FFMA/ALU only (no MUFU). rel err ~2e-6.
__device__ __forceinline__ float fexp(float x) {
    float t = fmaxf(x * 1.4426950408889634f, -126.0f);   // log2(e)*x, clamped
    float tr = t + 12582912.0f;                           // round-to-nearest-int magic
    int   n  = __float_as_int(tr) - 0x4B400000;           // integer part
    float f  = t - (tr - 12582912.0f);                    // frac in [-0.5, 0.5]
    float p = 0.0013333558f;
    p = fmaf(p, f, 0.0096181291f);
    p = fmaf(p, f, 0.0555041087f);
    p = fmaf(p, f, 0.2402265069f);
    p = fmaf(p, f, 0.6931471806f);
    p = fmaf(p, f, 1.0f);
    return p * __int_as_float((n + 127) << 23);           // p * 2^n
}

// ---------------------------------------------------------------------------
// TF32 tensor-core GEMM: C[M,N] = A[M,K] @ B[K,N] + bias[N]  (unchanged R4)
// ---------------------------------------------------------------------------
#define BMg 128
#define BNg 128
#define BKg 16
#define STAGES 3
#define A_STRIDE (BKg + 4)
#define B_STRIDE (BNg + 4)
#define AS_TILE (BMg * A_STRIDE)
#define BS_TILE (BKg * B_STRIDE)
#define SMEM_GEMM ((STAGES * (AS_TILE + BS_TILE)) * 4)

__global__ __launch_bounds__(256, 2)
void gemm_tf32_bias(const float* __restrict__ A, const float* __restrict__ B,
                    const float* __restrict__ bias, float* __restrict__ C,
                    int M, int N, int K) {
    extern __shared__ float smg[];
    float* AsBase = smg;
    float* BsBase = smg + STAGES * AS_TILE;

    int tid  = threadIdx.x;
    int wid  = tid >> 5;
    int lane = tid & 31;
    int warp_m = wid & 3;
    int warp_n = wid >> 2;
    int brow = blockIdx.y * BMg;
    int bcol = blockIdx.x * BNg;

    int a_row = tid >> 1;
    int a_col = (tid & 1) * 8;
    int b_row = tid >> 4;
    int b_col = (tid & 15) * 8;

    const float* Ap = A + (size_t)(brow + a_row) * K + a_col;
    const float* Bp = B + (size_t)b_row * N + bcol + b_col;

    wmma::fragment<wmma::accumulator, 16, 16, 8, float> acc[2][4];
#pragma unroll
    for (int i = 0; i < 2; i++)
#pragma unroll
        for (int j = 0; j < 4; j++) wmma::fill_fragment(acc[i][j], 0.0f);

    const int iters = K / BKg;

#pragma unroll
    for (int s = 0; s < STAGES - 1; s++) {
        int k0 = s * BKg;
        float* As = AsBase + s * AS_TILE;
        float* Bs = BsBase + s * BS_TILE;
        cp_async16(&As[a_row * A_STRIDE + a_col],     Ap + k0);
        cp_async16(&As[a_row * A_STRIDE + a_col + 4], Ap + k0 + 4);
        cp_async16(&Bs[b_row * B_STRIDE + b_col],     Bp + (size_t)k0 * N);
        cp_async16(&Bs[b_row * B_STRIDE + b_col + 4], Bp + (size_t)k0 * N + 4);
        cp_commit();
    }

    for (int it = 0; it < iters; it++) {
        cp_wait1();
        __syncthreads();

        int buf = it % STAGES;
        float* As = AsBase + buf * AS_TILE;
        float* Bs = BsBase + buf * BS_TILE;

#pragma unroll
        for (int kk = 0; kk < BKg; kk += 8) {
            wmma::fragment<wmma::matrix_a, 16, 16, 8, wmma::precision::tf32, wmma::row_major> af[2];
            wmma::fragment<wmma::matrix_b, 16, 16, 8, wmma::precision::tf32, wmma::row_major> bf[4];
#pragma unroll
            for (int i = 0; i < 2; i++) {
                wmma::load_matrix_sync(af[i], &As[(warp_m * 32 + i * 16) * A_STRIDE + kk], A_STRIDE);
#pragma unroll
                for (int t = 0; t < af[i].num_elements; t++)
                    af[i].x[t] = wmma::__float_to_tf32(af[i].x[t]);
            }
#pragma unroll
            for (int j = 0; j < 4; j++) {
                wmma::load_matrix_sync(bf[j], &Bs[kk * B_STRIDE + warp_n * 64 + j * 16], B_STRIDE);
#pragma unroll
                for (int t = 0; t < bf[j].num_elements; t++)
                    bf[j].x[t] = wmma::__float_to_tf32(bf[j].x[t]);
            }
#pragma unroll
            for (int i = 0; i < 2; i++)
#pragma unroll
                for (int j = 0; j < 4; j++)
                    wmma::mma_sync(acc[i][j], af[i], bf[j], acc[i][j]);
        }

        int k_next = (it + STAGES - 1) * BKg;
        if (k_next < K) {
            int s = (it + STAGES - 1) % STAGES;
            float* Asn = AsBase + s * AS_TILE;
            float* Bsn = BsBase + s * BS_TILE;
            cp_async16(&Asn[a_row * A_STRIDE + a_col],     Ap + k_next);
            cp_async16(&Asn[a_row * A_STRIDE + a_col + 4], Ap + k_next + 4);
            cp_async16(&Bsn[b_row * B_STRIDE + b_col],     Bp + (size_t)k_next * N);
            cp_async16(&Bsn[b_row * B_STRIDE + b_col + 4], Bp + (size_t)k_next * N + 4);
        }
        cp_commit();
    }

    __syncthreads();
    float* stg = AsBase + wid * 16 * 24;

    int er = lane >> 1;
    int ec = (lane & 1) * 8;
#pragma unroll
    for (int i = 0; i < 2; i++) {
#pragma unroll
        for (int j = 0; j < 4; j++) {
            wmma::store_matrix_sync(stg, acc[i][j], 24, wmma::mem_row_major);
            __syncwarp();
            int gr = brow + warp_m * 32 + i * 16 + er;
            int gc = bcol + warp_n * 64 + j * 16 + ec;
            float4 v0 = *(float4*)&stg[er * 24 + ec];
            float4 v1 = *(float4*)&stg[er * 24 + ec + 4];
            const float4 bb0 = *(const float4*)&bias[gc];
            const float4 bb1 = *(const float4*)&bias[gc + 4];
            v0.x += bb0.x; v0.y += bb0.y; v0.z += bb0.z; v0.w += bb0.w;
            v1.x += bb1.x; v1.y += bb1.y; v1.z += bb1.z; v1.w += bb1.w;
            *(float4*)(C + (size_t)gr * N + gc)     = v0;
            *(float4*)(C + (size_t)gr * N + gc + 4) = v1;
            __syncwarp();
        }
    }
}

// ---------------------------------------------------------------------------
// RoPE + split qkv[BT, 3D] -> Q,K,V in [B,H,T,DH]
// ---------------------------------------------------------------------------
__global__ __launch_bounds__(256)
void rope_split_kernel(const float* __restrict__ qkv,
                       float* __restrict__ Q, float* __restrict__ K,
                       float* __restrict__ V) {
    int idx = blockIdx.x * blockDim.x + threadIdx.x;
    const int total = BB * TT * HH * (DH / 2);
    if (idx >= total) return;
    int d2 = idx & 31;
    int h  = (idx >> 5) & (HH - 1);
    int t  = (idx >> 9) & (TT - 1);
    int b  = idx >> 20;

    size_t row = (size_t)b * TT + t;
    const float* qr = qkv + row * (3 * DD) + h * DH + 2 * d2;
    const float* kr = qr + DD;
    const float* vr = qr + 2 * DD;

    float inv_freq = powf(10000.0f, -((float)(2 * d2)) / (float)DH);
    float freq = (float)t * inv_freq;
    float s = sinf(freq);
    float c = cosf(freq);

    float qe = qr[0], qo = qr[1];
    float ke = kr[0], ko = kr[1];

    size_t o = ((((size_t)b * HH + h) * TT) + t) * DH + 2 * d2;
    Q[o]     = qe * c - qo * s;
    Q[o + 1] = qe * s + qo * c;
    K[o]     = ke * c - ko * s;
    K[o + 1] = ke * s + ko * c;
    V[o]     = vr[0];
    V[o + 1] = vr[1];
}

// ---------------------------------------------------------------------------
// WMMA flash attention: 64-query tile per block, 256 threads (8 warps).
// S = Q*K^T via 3xtf32 (fp32-accurate); O += P*V via tf32 (V hi/lo split).
// O tile lives in smem; scalar softmax rescales it per key tile.
// Softmax exp is FFMA-only (fexp) -> no MUFU bottleneck.
// ---------------------------------------------------------------------------
#define FS 68
#define SMEM_FLASH ((5 * 64 * FS) * 4 + 64 * 4)

__global__ __launch_bounds__(256, 2)
void flash_attn_wmma(const float* __restrict__ Q, const float* __restrict__ K,
                     const float* __restrict__ V, const int* __restrict__ mask,
                     float* __restrict__ Out) {
    extern __shared__ __align__(32) float sm[];
    float* Qs = sm;                  // [64][FS] prescaled by 0.125
    float* Ks = Qs + 64 * FS;        // [64][FS]
    float* Vs = Ks + 64 * FS;        // [64][FS]
    float* Ss = Vs + 64 * FS;        // [64][FS] scores then probs
    float* Os = Ss + 64 * FS;        // [64][FS] running output
    int*   ms = (int*)(Os + 64 * FS);

    int b = blockIdx.z, h = blockIdx.y;
    int qtile = gridDim.x - 1 - blockIdx.x;   // heavy tiles first
    int qbase = qtile * 64;
    int tid = threadIdx.x;
    int wid = tid >> 5;
    int warp_m = wid & 3;        // 16-row block of the 64x64 tile
    int warp_n = wid >> 2;       // 32-col block
    int ty = tid >> 4;           // 0..15 -> rows ty*4..ty*4+3
    int tx = tid & 15;           // 0..15 -> cols tx*4..tx*4+3

    const size_t bh = ((size_t)b * HH + h) * TT;
    const float* Qb = Q + bh * DH;
    const float* Kb = K + bh * DH;
    const float* Vb = V + bh * DH;

    // Load Q tile (scaled), zero O tile
    {
        int r = tid >> 2;
        int c = (tid & 3) * 16;
        const float* src = Qb + (size_t)(qbase + r) * DH + c;
#pragma unroll
        for (int u = 0; u < 4; u++) {
            float4 v = *(const float4*)(src + u * 4);
            v.x *= 0.125f; v.y *= 0.125f; v.z *= 0.125f; v.w *= 0.125f;
            *(float4*)&Qs[r * FS + c + u * 4] = v;
            *(float4*)&Os[r * FS + c + u * 4] = make_float4(0.f, 0.f, 0.f, 0.f);
        }
    }

    float m_r[4], l_r[4];
#pragma unroll
    for (int i = 0; i < 4; i++) { m_r[i] = -1e30f; l_r[i] = 0.f; }

    for (int kt = 0; kt <= qbase; kt += 64) {
        __syncthreads();   // prior-iter PV reads of Ss, loads of Ks/Vs done

        // Load K and V tiles (coalesced, natural layout)
        {
            int r = tid >> 2;
            int c = (tid & 3) * 16;
            const float* ksrc = Kb + (size_t)(kt + r) * DH + c;
            const float* vsrc = Vb + (size_t)(kt + r) * DH + c;
#pragma unroll
            for (int u = 0; u < 4; u++) {
                *(float4*)&Ks[r * FS + c + u * 4] = *(const float4*)(ksrc + u * 4);
                *(float4*)&Vs[r * FS + c + u * 4] = *(const float4*)(vsrc + u * 4);
            }
        }
        if (tid < 64) ms[tid] = mask[b * TT + kt + tid];
        __syncthreads();

        // ---- S = Q * K^T, 3xtf32 ----
        {
            wmma::fragment<wmma::accumulator, 16, 16, 8, float> s_acc[2];
#pragma unroll
            for (int n = 0; n < 2; n++) wmma::fill_fragment(s_acc[n], 0.0f);

#pragma unroll
            for (int k0 = 0; k0 < DH; k0 += 8) {
                wmma::fragment<wmma::matrix_a, 16, 16, 8, wmma::precision::tf32, wmma::row_major> a_hi, a_lo;
                wmma::load_matrix_sync(a_hi, &Qs[(warp_m * 16) * FS + k0], FS);
#pragma unroll
                for (int t = 0; t < a_hi.num_elements; t++) {
                    float r = a_hi.x[t];
                    float hh = wmma::__float_to_tf32(r);
                    a_hi.x[t] = hh;
                    a_lo.x[t] = wmma::__float_to_tf32(r - hh);
                }
                wmma::fragment<wmma::matrix_b, 16, 16, 8, wmma::precision::tf32, wmma::col_major> b_hi[2], b_lo[2];
#pragma unroll
                for (int n = 0; n < 2; n++) {
                    wmma::load_matrix_sync(b_hi[n], &Ks[(warp_n * 32 + n * 16) * FS + k0], FS);
#pragma unroll
                    for (int t = 0; t < b_hi[n].num_elements; t++) {
                        float r = b_hi[n].x[t];
                        float hh = wmma::__float_to_tf32(r);
                        b_hi[n].x[t] = hh;
                        b_lo[n].x[t] = wmma::__float_to_tf32(r - hh);
                    }
                }
#pragma unroll
                for (int n = 0; n < 2; n++) {
                    wmma::mma_sync(s_acc[n], a_hi, b_lo[n], s_acc[n]);
                    wmma::mma_sync(s_acc[n], a_lo, b_hi[n], s_acc[n]);
                    wmma::mma_sync(s_acc[n], a_hi, b_hi[n], s_acc[n]);
                }
            }
#pragma unroll
            for (int n = 0; n < 2; n++)
                wmma::store_matrix_sync(&Ss[(warp_m * 16) * FS + warp_n * 32 + n * 16],
                                        s_acc[n], FS, wmma::mem_row_major);
        }
        __syncthreads();

        // ---- Online softmax (scalar, fexp) + rescale O tile ----
        bool diag = (kt == qbase);
#pragma unroll
        for (int i = 0; i < 4; i++) {
            int row = ty * 4 + i;
            float sv[4];
            float rmax = -1e30f;
#pragma unroll
            for (int j = 0; j < 4; j++) {
                int jl = tx * 4 + j;
                bool ok = (ms[jl] != 0) && (!diag || jl <= row);
                float s = ok ? Ss[row * FS + jl] : -1e30f;
                sv[j] = s;
                rmax = fmaxf(rmax, s);
            }
#pragma unroll
            for (int off = 8; off >= 1; off >>= 1)
                rmax = fmaxf(rmax, __shfl_xor_sync(0xffffffffu, rmax, off, 16));
            float m_new = fmaxf(m_r[i], rmax);
            float rsum = 0.f;
#pragma unroll
            for (int j = 0; j < 4; j++) {
                float p = fexp(sv[j] - m_new);
                Ss[row * FS + tx * 4 + j] = p;
                rsum += p;
            }
#pragma unroll
            for (int off = 8; off >= 1; off >>= 1)
                rsum += __shfl_xor_sync(0xffffffffu, rsum, off, 16);
            float scale = fexp(m_r[i] - m_new);
            l_r[i] = l_r[i] * scale + rsum;
            m_r[i] = m_new;
#pragma unroll
            for (int j = 0; j < 4; j++)
                Os[row * FS + tx * 4 + j] *= scale;
        }
        __syncthreads();

        // ---- O += P * V  (P single tf32, V hi/lo) ----
        {
            wmma::fragment<wmma::accumulator, 16, 16, 8, float> o_acc[2];
#pragma unroll
            for (int n = 0; n < 2; n++)
                wmma::load_matrix_sync(o_acc[n], &Os[(warp_m * 16) * FS + warp_n * 32 + n * 16],
                                       FS, wmma::mem_row_major);

#pragma unroll
            for (int k0 = 0; k0 < 64; k0 += 8) {
                wmma::fragment<wmma::matrix_a, 16, 16, 8, wmma::precision::tf32, wmma::row_major> pf;
                wmma::load_matrix_sync(pf, &Ss[(warp_m * 16) * FS + k0], FS);
#pragma unroll
                for (int t = 0; t < pf.num_elements; t++)
                    pf.x[t] = wmma::__float_to_tf32(pf.x[t]);
                wmma::fragment<wmma::matrix_b, 16, 16, 8, wmma::precision::tf32, wmma::row_major> v_hi[2], v_lo[2];
#pragma unroll
                for (int n = 0; n < 2; n++) {
                    wmma::load_matrix_sync(v_hi[n], &Vs[k0 * FS + warp_n * 32 + n * 16], FS);
#pragma unroll
                    for (int t = 0; t < v_hi[n].num_elements; t++) {
                        float r = v_hi[n].x[t];
                        float hh = wmma::__float_to_tf32(r);
                        v_hi[n].x[t] = hh;
                        v_lo[n].x[t] = wmma::__float_to_tf32(r - hh);
                    }
                }
#pragma unroll
                for (int n = 0; n < 2; n++) {
                    wmma::mma_sync(o_acc[n], pf, v_lo[n], o_acc[n]);
                    wmma::mma_sync(o_acc[n], pf, v_hi[n], o_acc[n]);
                }
            }
#pragma unroll
            for (int n = 0; n < 2; n++)
                wmma::store_matrix_sync(&Os[(warp_m * 16) * FS + warp_n * 32 + n * 16],
                                        o_acc[n], FS, wmma::mem_row_major);
        }
    }
    __syncthreads();

    // Epilogue: normalize, write [B*T, D] at head offset
#pragma unroll
    for (int i = 0; i < 4; i++) {
        int row = ty * 4 + i;
        float inv = (l_r[i] > 0.f) ? (1.0f / l_r[i]) : 0.f;
        float4 o4;
        o4.x = Os[row * FS + tx * 4 + 0] * inv;
        o4.y = Os[row * FS + tx * 4 + 1] * inv;
        o4.z = Os[row * FS + tx * 4 + 2] * inv;
        o4.w = Os[row * FS + tx * 4 + 3] * inv;
        *(float4*)(Out + ((size_t)(b * TT + qbase + row)) * DD + h * DH + tx * 4) = o4;
    }
}

// ---------------------------------------------------------------------------
extern "C" void kernel_launch(void* const* d_in, const int* in_sizes, int n_in,
                              void* d_out, int out_size) {
    const float* x     = (const float*)d_in[0];
    const int*   amask = (const int*)d_in[1];
    const float* Wqkv  = (const float*)d_in[2];
    const float* bqkv  = (const float*)d_in[3];
    const float* Wout  = (const float*)d_in[4];
    const float* bout  = (const float*)d_in[5];
    float* out = (float*)d_out;

    float *qkv, *Qp, *Kp, *Vp, *Att;
    cudaGetSymbolAddress((void**)&qkv, g_qkv);
    cudaGetSymbolAddress((void**)&Qp,  g_q);
    cudaGetSymbolAddress((void**)&Kp,  g_k);
    cudaGetSymbolAddress((void**)&Vp,  g_v);
    cudaGetSymbolAddress((void**)&Att, g_att);

    static bool attr_set = false;
    if (!attr_set) {
        cudaFuncSetAttribute(flash_attn_wmma,
                             cudaFuncAttributeMaxDynamicSharedMemorySize,
                             SMEM_FLASH);
        cudaFuncSetAttribute(gemm_tf32_bias,
                             cudaFuncAttributeMaxDynamicSharedMemorySize,
                             SMEM_GEMM);
        attr_set = true;
    }

    // 1) QKV projection
    {
        dim3 grid(3 * DD / BNg, BT / BMg);
        gemm_tf32_bias<<<grid, 256, SMEM_GEMM>>>(x, Wqkv, bqkv, qkv, BT, 3 * DD, DD);
    }
    // 2) RoPE + split
    {
        int total = BB * TT * HH * (DH / 2);
        rope_split_kernel<<<(total + 255) / 256, 256>>>(qkv, Qp, Kp, Vp);
    }
    // 3) WMMA flash attention
    {
        dim3 grid(TT / 64, HH, BB);
        flash_attn_wmma<<<grid, 256, SMEM_FLASH>>>(Qp, Kp, Vp, amask, Att);
    }
    // 4) Output projection
    {
        dim3 grid(DD / BNg, BT / BMg);
        gemm_tf32_bias<<<grid, 256, SMEM_GEMM>>>(Att, Wout, bout, out, BT, DD, DD);
    }
}

// round 7
// speedup vs baseline: 1.1500x; 1.1500x over previous
#include <cuda_runtime.h>
#include <stdint.h>
#include <math.h>
#include <mma.h>

using namespace nvcuda;

#define BB 2
#define TT 2048
#define DD 1024
#define HH 16
#define DH 64
#define BT (BB*TT)

// Scratch (allocation-free rule: __device__ globals)
__device__ float g_qkv[(size_t)BT * 3 * DD];
__device__ float g_q[(size_t)BT * DD];   // [B,H,T,DH]
__device__ float g_k[(size_t)BT * DD];
__device__ float g_v[(size_t)BT * DD];
__device__ float g_att[(size_t)BT * DD]; // [B*T, D]

// ---------------------------------------------------------------------------
// cp.async helpers
// ---------------------------------------------------------------------------
__device__ __forceinline__ void cp_async16(void* dst, const void* src) {
    unsigned int d = (unsigned int)__cvta_generic_to_shared(dst);
    asm volatile("cp.async.ca.shared.global [%0], [%1], 16;\n" :: "r"(d), "l"(src));
}
__device__ __forceinline__ void cp_commit() {
    asm volatile("cp.async.commit_group;\n");
}
__device__ __forceinline__ void cp_wait1() {
    asm volatile("cp.async.wait_group 1;\n");
}

// Fast exp for x <= 0: FFMA/ALU only (no MUFU). rel err ~2e-6.
__device__ __forceinline__ float fexp(float x) {
    float t = fmaxf(x * 1.4426950408889634f, -126.0f);   // log2(e)*x, clamped
    float tr = t + 12582912.0f;                           // round-to-nearest-int magic
    int   n  = __float_as_int(tr) - 0x4B400000;           // integer part
    float f  = t - (tr - 12582912.0f);                    // frac in [-0.5, 0.5]
    float p = 0.0013333558f;
    p = fmaf(p, f, 0.0096181291f);
    p = fmaf(p, f, 0.0555041087f);
    p = fmaf(p, f, 0.2402265069f);
    p = fmaf(p, f, 0.6931471806f);
    p = fmaf(p, f, 1.0f);
    return p * __int_as_float((n + 127) << 23);           // p * 2^n
}

// ---------------------------------------------------------------------------
// TF32 tensor-core GEMM: C[M,N] = A[M,K] @ B[K,N] + bias[N]  (unchanged R4)
// ---------------------------------------------------------------------------
#define BMg 128
#define BNg 128
#define BKg 16
#define STAGES 3
#define A_STRIDE (BKg + 4)
#define B_STRIDE (BNg + 4)
#define AS_TILE (BMg * A_STRIDE)
#define BS_TILE (BKg * B_STRIDE)
#define SMEM_GEMM ((STAGES * (AS_TILE + BS_TILE)) * 4)

__global__ __launch_bounds__(256, 2)
void gemm_tf32_bias(const float* __restrict__ A, const float* __restrict__ B,
                    const float* __restrict__ bias, float* __restrict__ C,
                    int M, int N, int K) {
    extern __shared__ float smg[];
    float* AsBase = smg;
    float* BsBase = smg + STAGES * AS_TILE;

    int tid  = threadIdx.x;
    int wid  = tid >> 5;
    int lane = tid & 31;
    int warp_m = wid & 3;
    int warp_n = wid >> 2;
    int brow = blockIdx.y * BMg;
    int bcol = blockIdx.x * BNg;

    int a_row = tid >> 1;
    int a_col = (tid & 1) * 8;
    int b_row = tid >> 4;
    int b_col = (tid & 15) * 8;

    const float* Ap = A + (size_t)(brow + a_row) * K + a_col;
    const float* Bp = B + (size_t)b_row * N + bcol + b_col;

    wmma::fragment<wmma::accumulator, 16, 16, 8, float> acc[2][4];
#pragma unroll
    for (int i = 0; i < 2; i++)
#pragma unroll
        for (int j = 0; j < 4; j++) wmma::fill_fragment(acc[i][j], 0.0f);

    const int iters = K / BKg;

#pragma unroll
    for (int s = 0; s < STAGES - 1; s++) {
        int k0 = s * BKg;
        float* As = AsBase + s * AS_TILE;
        float* Bs = BsBase + s * BS_TILE;
        cp_async16(&As[a_row * A_STRIDE + a_col],     Ap + k0);
        cp_async16(&As[a_row * A_STRIDE + a_col + 4], Ap + k0 + 4);
        cp_async16(&Bs[b_row * B_STRIDE + b_col],     Bp + (size_t)k0 * N);
        cp_async16(&Bs[b_row * B_STRIDE + b_col + 4], Bp + (size_t)k0 * N + 4);
        cp_commit();
    }

    for (int it = 0; it < iters; it++) {
        cp_wait1();
        __syncthreads();

        int buf = it % STAGES;
        float* As = AsBase + buf * AS_TILE;
        float* Bs = BsBase + buf * BS_TILE;

#pragma unroll
        for (int kk = 0; kk < BKg; kk += 8) {
            wmma::fragment<wmma::matrix_a, 16, 16, 8, wmma::precision::tf32, wmma::row_major> af[2];
            wmma::fragment<wmma::matrix_b, 16, 16, 8, wmma::precision::tf32, wmma::row_major> bf[4];
#pragma unroll
            for (int i = 0; i < 2; i++) {
                wmma::load_matrix_sync(af[i], &As[(warp_m * 32 + i * 16) * A_STRIDE + kk], A_STRIDE);
#pragma unroll
                for (int t = 0; t < af[i].num_elements; t++)
                    af[i].x[t] = wmma::__float_to_tf32(af[i].x[t]);
            }
#pragma unroll
            for (int j = 0; j < 4; j++) {
                wmma::load_matrix_sync(bf[j], &Bs[kk * B_STRIDE + warp_n * 64 + j * 16], B_STRIDE);
#pragma unroll
                for (int t = 0; t < bf[j].num_elements; t++)
                    bf[j].x[t] = wmma::__float_to_tf32(bf[j].x[t]);
            }
#pragma unroll
            for (int i = 0; i < 2; i++)
#pragma unroll
                for (int j = 0; j < 4; j++)
                    wmma::mma_sync(acc[i][j], af[i], bf[j], acc[i][j]);
        }

        int k_next = (it + STAGES - 1) * BKg;
        if (k_next < K) {
            int s = (it + STAGES - 1) % STAGES;
            float* Asn = AsBase + s * AS_TILE;
            float* Bsn = BsBase + s * BS_TILE;
            cp_async16(&Asn[a_row * A_STRIDE + a_col],     Ap + k_next);
            cp_async16(&Asn[a_row * A_STRIDE + a_col + 4], Ap + k_next + 4);
            cp_async16(&Bsn[b_row * B_STRIDE + b_col],     Bp + (size_t)k_next * N);
            cp_async16(&Bsn[b_row * B_STRIDE + b_col + 4], Bp + (size_t)k_next * N + 4);
        }
        cp_commit();
    }

    __syncthreads();
    float* stg = AsBase + wid * 16 * 24;

    int er = lane >> 1;
    int ec = (lane & 1) * 8;
#pragma unroll
    for (int i = 0; i < 2; i++) {
#pragma unroll
        for (int j = 0; j < 4; j++) {
            wmma::store_matrix_sync(stg, acc[i][j], 24, wmma::mem_row_major);
            __syncwarp();
            int gr = brow + warp_m * 32 + i * 16 + er;
            int gc = bcol + warp_n * 64 + j * 16 + ec;
            float4 v0 = *(float4*)&stg[er * 24 + ec];
            float4 v1 = *(float4*)&stg[er * 24 + ec + 4];
            const float4 bb0 = *(const float4*)&bias[gc];
            const float4 bb1 = *(const float4*)&bias[gc + 4];
            v0.x += bb0.x; v0.y += bb0.y; v0.z += bb0.z; v0.w += bb0.w;
            v1.x += bb1.x; v1.y += bb1.y; v1.z += bb1.z; v1.w += bb1.w;
            *(float4*)(C + (size_t)gr * N + gc)     = v0;
            *(float4*)(C + (size_t)gr * N + gc + 4) = v1;
            __syncwarp();
        }
    }
}

// ---------------------------------------------------------------------------
// RoPE + split qkv[BT, 3D] -> Q,K,V in [B,H,T,DH]
// ---------------------------------------------------------------------------
__global__ __launch_bounds__(256)
void rope_split_kernel(const float* __restrict__ qkv,
                       float* __restrict__ Q, float* __restrict__ K,
                       float* __restrict__ V) {
    int idx = blockIdx.x * blockDim.x + threadIdx.x;
    const int total = BB * TT * HH * (DH / 2);
    if (idx >= total) return;
    int d2 = idx & 31;
    int h  = (idx >> 5) & (HH - 1);
    int t  = (idx >> 9) & (TT - 1);
    int b  = idx >> 20;

    size_t row = (size_t)b * TT + t;
    const float* qr = qkv + row * (3 * DD) + h * DH + 2 * d2;
    const float* kr = qr + DD;
    const float* vr = qr + 2 * DD;

    float inv_freq = powf(10000.0f, -((float)(2 * d2)) / (float)DH);
    float freq = (float)t * inv_freq;
    float s = sinf(freq);
    float c = cosf(freq);

    float qe = qr[0], qo = qr[1];
    float ke = kr[0], ko = kr[1];

    size_t o = ((((size_t)b * HH + h) * TT) + t) * DH + 2 * d2;
    Q[o]     = qe * c - qo * s;
    Q[o + 1] = qe * s + qo * c;
    K[o]     = ke * c - ko * s;
    K[o + 1] = ke * s + ko * c;
    V[o]     = vr[0];
    V[o + 1] = vr[1];
}

// ---------------------------------------------------------------------------
// Tiled flash attention (R4 structure) + FFMA-only exp (no MUFU).
// 64-query tile per block, 256 threads, scalar 4x4 register tile GEMMs.
// ---------------------------------------------------------------------------
#define QS_STRIDE 65
#define VS_STRIDE 68
#define SMEM_FLASH ((2 * 64 * QS_STRIDE + 64 * VS_STRIDE) * 4 + 64 * 4)

__device__ __forceinline__ void load_tile_T(const float* __restrict__ src,
                                            float* __restrict__ dst,
                                            int tid, float mul) {
    int r = tid >> 2;
    int cbase = (tid & 3) * 4;
#pragma unroll
    for (int rep = 0; rep < 4; rep++) {
        int c = cbase + rep * 16;
        float4 v = *(const float4*)(src + r * 64 + c);
        dst[(c + 0) * QS_STRIDE + r] = v.x * mul;
        dst[(c + 1) * QS_STRIDE + r] = v.y * mul;
        dst[(c + 2) * QS_STRIDE + r] = v.z * mul;
        dst[(c + 3) * QS_STRIDE + r] = v.w * mul;
    }
}

__global__ __launch_bounds__(256)
void flash_attn_tiled(const float* __restrict__ Q, const float* __restrict__ K,
                      const float* __restrict__ V, const int* __restrict__ mask,
                      float* __restrict__ Out) {
    extern __shared__ float sm[];
    float* Qs  = sm;
    float* KPs = sm + 64 * QS_STRIDE;
    float* Vs  = sm + 2 * 64 * QS_STRIDE;
    int*   ms  = (int*)(sm + 2 * 64 * QS_STRIDE + 64 * VS_STRIDE);

    int b = blockIdx.z, h = blockIdx.y;
    int qtile = gridDim.x - 1 - blockIdx.x;
    int qbase = qtile * 64;
    int tid = threadIdx.x;
    int ty = tid >> 4;
    int tx = tid & 15;

    const size_t bh = ((size_t)b * HH + h) * TT;
    const float* Qb = Q + bh * DH;
    const float* Kb = K + bh * DH;
    const float* Vb = V + bh * DH;

    load_tile_T(Qb + (size_t)qbase * DH, Qs, tid, 0.125f);

    float acc_o[4][4];
    float m_r[4], l_r[4];
#pragma unroll
    for (int i = 0; i < 4; i++) {
        m_r[i] = -1e30f;
        l_r[i] = 0.f;
#pragma unroll
        for (int j = 0; j < 4; j++) acc_o[i][j] = 0.f;
    }

    for (int kt = 0; kt <= qbase; kt += 64) {
        __syncthreads();

        load_tile_T(Kb + (size_t)kt * DH, KPs, tid, 1.0f);
        {
            int j = tid >> 4;
            int c = (tid & 15) * 4;
#pragma unroll
            for (int rep = 0; rep < 4; rep++) {
                float4 v = *(const float4*)(Vb + (size_t)(kt + j + rep * 16) * DH + c);
                *(float4*)&Vs[(j + rep * 16) * VS_STRIDE + c] = v;
            }
        }
        if (tid < 64) ms[tid] = mask[b * TT + kt + tid];
        __syncthreads();

        float acc_s[4][4];
#pragma unroll
        for (int i = 0; i < 4; i++)
#pragma unroll
            for (int j = 0; j < 4; j++) acc_s[i][j] = 0.f;

        for (int kk = 0; kk < 64; kk++) {
            float ra[4], rb[4];
#pragma unroll
            for (int i = 0; i < 4; i++) ra[i] = Qs[kk * QS_STRIDE + ty * 4 + i];
#pragma unroll
            for (int j = 0; j < 4; j++) rb[j] = KPs[kk * QS_STRIDE + tx * 4 + j];
#pragma unroll
            for (int i = 0; i < 4; i++)
#pragma unroll
                for (int j = 0; j < 4; j++) acc_s[i][j] += ra[i] * rb[j];
        }
        __syncthreads();

        bool diag = (kt == qbase);

#pragma unroll
        for (int i = 0; i < 4; i++) {
            int il = ty * 4 + i;
            float rmax = -1e30f;
#pragma unroll
            for (int j = 0; j < 4; j++) {
                int jl = tx * 4 + j;
                bool ok = (ms[jl] != 0) && (!diag || jl <= il);
                float s = ok ? acc_s[i][j] : -1e30f;
                acc_s[i][j] = s;
                rmax = fmaxf(rmax, s);
            }
#pragma unroll
            for (int off = 8; off >= 1; off >>= 1)
                rmax = fmaxf(rmax, __shfl_xor_sync(0xffffffffu, rmax, off, 16));
            float m_new = fmaxf(m_r[i], rmax);
            float rsum = 0.f;
#pragma unroll
            for (int j = 0; j < 4; j++) {
                float p = fexp(acc_s[i][j] - m_new);
                acc_s[i][j] = p;
                rsum += p;
            }
#pragma unroll
            for (int off = 8; off >= 1; off >>= 1)
                rsum += __shfl_xor_sync(0xffffffffu, rsum, off, 16);
            float scale = fexp(m_r[i] - m_new);
            l_r[i] = l_r[i] * scale + rsum;
            m_r[i] = m_new;
#pragma unroll
            for (int j = 0; j < 4; j++) acc_o[i][j] *= scale;
        }

#pragma unroll
        for (int i = 0; i < 4; i++)
#pragma unroll
            for (int j = 0; j < 4; j++)
                KPs[(ty * 4 + i) * QS_STRIDE + tx * 4 + j] = acc_s[i][j];
        __syncthreads();

        for (int j = 0; j < 64; j++) {
            float4 vb = *(const float4*)&Vs[j * VS_STRIDE + tx * 4];
            float pa[4];
#pragma unroll
            for (int i = 0; i < 4; i++) pa[i] = KPs[(ty * 4 + i) * QS_STRIDE + j];
#pragma unroll
            for (int i = 0; i < 4; i++) {
                acc_o[i][0] += pa[i] * vb.x;
                acc_o[i][1] += pa[i] * vb.y;
                acc_o[i][2] += pa[i] * vb.z;
                acc_o[i][3] += pa[i] * vb.w;
            }
        }
    }

#pragma unroll
    for (int i = 0; i < 4; i++) {
        int il = ty * 4 + i;
        float inv = (l_r[i] > 0.f) ? (1.0f / l_r[i]) : 0.f;
        float4 o4;
        o4.x = acc_o[i][0] * inv;
        o4.y = acc_o[i][1] * inv;
        o4.z = acc_o[i][2] * inv;
        o4.w = acc_o[i][3] * inv;
        *(float4*)(Out + ((size_t)(b * TT + qbase + il)) * DD + h * DH + tx * 4) = o4;
    }
}

// ---------------------------------------------------------------------------
extern "C" void kernel_launch(void* const* d_in, const int* in_sizes, int n_in,
                              void* d_out, int out_size) {
    const float* x     = (const float*)d_in[0];
    const int*   amask = (const int*)d_in[1];
    const float* Wqkv  = (const float*)d_in[2];
    const float* bqkv  = (const float*)d_in[3];
    const float* Wout  = (const float*)d_in[4];
    const float* bout  = (const float*)d_in[5];
    float* out = (float*)d_out;

    float *qkv, *Qp, *Kp, *Vp, *Att;
    cudaGetSymbolAddress((void**)&qkv, g_qkv);
    cudaGetSymbolAddress((void**)&Qp,  g_q);
    cudaGetSymbolAddress((void**)&Kp,  g_k);
    cudaGetSymbolAddress((void**)&Vp,  g_v);
    cudaGetSymbolAddress((void**)&Att, g_att);

    static bool attr_set = false;
    if (!attr_set) {
        cudaFuncSetAttribute(flash_attn_tiled,
                             cudaFuncAttributeMaxDynamicSharedMemorySize,
                             SMEM_FLASH);
        cudaFuncSetAttribute(gemm_tf32_bias,
                             cudaFuncAttributeMaxDynamicSharedMemorySize,
                             SMEM_GEMM);
        attr_set = true;
    }

    // 1) QKV projection
    {
        dim3 grid(3 * DD / BNg, BT / BMg);
        gemm_tf32_bias<<<grid, 256, SMEM_GEMM>>>(x, Wqkv, bqkv, qkv, BT, 3 * DD, DD);
    }
    // 2) RoPE + split
    {
        int total = BB * TT * HH * (DH / 2);
        rope_split_kernel<<<(total + 255) / 256, 256>>>(qkv, Qp, Kp, Vp);
    }
    // 3) Tiled flash attention (fexp)
    {
        dim3 grid(TT / 64, HH, BB);
        flash_attn_tiled<<<grid, 256, SMEM_FLASH>>>(Qp, Kp, Vp, amask, Att);
    }
    // 4) Output projection
    {
        dim3 grid(DD / BNg, BT / BMg);
        gemm_tf32_bias<<<grid, 256, SMEM_GEMM>>>(Att, Wout, bout, out, BT, DD, DD);
    }
}